// round 5
// baseline (speedup 1.0000x reference)
#include <cuda_runtime.h>

#define NTIME 1024
#define NB    65536
#define TPB   128

__global__ void __launch_bounds__(TPB)
bts_interp_kernel(const float* __restrict__ times,
                  const float* __restrict__ values,
                  const float* __restrict__ tq,
                  float* __restrict__ out)
{
    const int b = blockIdx.x * TPB + threadIdx.x;
    const float t = __ldg(&tq[b]);
    const float* col = times + b;

    // ---- Coarse stage: 32 coalesced rows 31, 63, ..., 1023 (ascending). ----
    // m = #coarse knots <= t  ->  count in [32m, 32m+32).
    // Track lo = last success (= times[32m-1]) and hi = first failure (= times[32m+31]).
    int   m  = 0;
    float lo = 0.0f;
    float hi = 0.0f;
#pragma unroll
    for (int chunk = 0; chunk < 4; ++chunk) {
        float x[8];
#pragma unroll
        for (int i = 0; i < 8; ++i)
            x[i] = __ldg(col + (size_t)(32 * (chunk * 8 + i) + 31) * NB);
#pragma unroll
        for (int i = 0; i < 8; ++i) {
            const int idx = chunk * 8 + i;
            if (x[i] <= t) { lo = x[i]; m++; }
            else if (idx == m) { hi = x[i]; }   // first failure only
        }
    }

    int c = m << 5;   // lower bound on count; m==32 -> count == 1024 (rare path).

    if (m < 32) {
        // ---- Fine stage: binary search within bucket of 32 (5 divergent probes).
        // Invariant: on success lo = probed knot = times[c_new - 1];
        //            on failure hi = probed knot; final hi == times[c] exactly.
#pragma unroll
        for (int step = 16; step >= 1; step >>= 1) {
            const float x = __ldg(col + (size_t)(c + step - 1) * NB);
            if (x <= t) { lo = x; c += step; }
            else        { hi = x; }
        }
    }

    const int gi = c & (NTIME - 1);   // c==0 or c==1024 -> gi==0 (wrap path)

    float result;
    if (gi != 0) {
        // Normal path: lo == times[gi-1], hi == times[gi] (bit-exact from probes).
        const float va = __ldg(&values[(size_t)(gi - 1) * NB + b]);
        const float vb = __ldg(&values[(size_t)gi       * NB + b]);
        const float s0 = (vb - va) / (hi - lo);
        result = va + s0 * (t - lo);
    } else {
        // Wrap path (count == 0 or 1024): iv = 1023, isl = 1022.
        const float t_prev = __ldg(&times [(size_t)(NTIME - 2) * NB + b]);
        const float t_last = __ldg(&times [(size_t)(NTIME - 1) * NB + b]);
        const float v_prev = __ldg(&values[(size_t)(NTIME - 2) * NB + b]);
        const float v_last = __ldg(&values[(size_t)(NTIME - 1) * NB + b]);
        const float s0 = (v_last - v_prev) / (t_last - t_prev);
        result = v_last + s0 * (t - t_last);
    }

    out[b] = result;
}

extern "C" void kernel_launch(void* const* d_in, const int* in_sizes, int n_in,
                              void* d_out, int out_size)
{
    const float* times  = (const float*)d_in[0];
    const float* values = (const float*)d_in[1];
    const float* tq     = (const float*)d_in[2];
    float* out = (float*)d_out;

    bts_interp_kernel<<<NB / TPB, TPB>>>(times, values, tq, out);
}